// round 1
// baseline (speedup 1.0000x reference)
#include <cuda_runtime.h>
#include <cstdint>

#define NT 2
#define NC 128
#define NH 96
#define NW 96
#define HW 9216        // 96*96
#define NQ 18432       // NT*HW
#define HEADS 4
#define HD 32
#define TILE 16
#define HALO 23        // 16 + 4 + 3
#define HALO_PIX 529   // 23*23
#define QSCALE 0.17677669529663687f
#define NEG_HUGE (-3.402823466e38f)

// ---------------- scratch (static device allocations) ----------------
__device__ __align__(16) float g_dw[3][NT][NC][HW];     // depthwise results q/k/v
__device__ __align__(16) float g_q[NT * HEADS * HD * HW];  // [t][h][d][pix]
__device__ __align__(16) float g_k[NT * HEADS * HD * HW];  // [t][h][d][pix]
__device__ __align__(16) float g_v[NT * HEADS * HD * HW];  // [t][h][d][pix]
__device__ __align__(16) float g_att[NQ * NC];             // [q][c], c = h*32+d

// ---------------- kernel 1: depthwise 3x3, zero-pad SAME, 3 projections ----------------
__global__ __launch_bounds__(256) void dw_kernel(
    const float* __restrict__ vid,
    const float* __restrict__ wq, const float* __restrict__ wk,
    const float* __restrict__ wv)
{
    int tx = threadIdx.x & 15, ty = threadIdx.x >> 4;
    int tr = (blockIdx.x / 6) * TILE, tc = (blockIdx.x % 6) * TILE;
    int t = blockIdx.y, cg = blockIdx.z;
    int gi = tr + ty, gj = tc + tx;
    int pix = gi * NW + gj;
    for (int cc = 0; cc < 16; cc++) {
        int c = cg * 16 + cc;
        const float* xp = vid + (t * NC + c) * HW;
        float sq = 0.f, sk = 0.f, sv = 0.f;
#pragma unroll
        for (int ky = 0; ky < 3; ky++) {
            int yy = gi + ky - 1;
#pragma unroll
            for (int kx = 0; kx < 3; kx++) {
                int xx = gj + kx - 1;
                float xv = 0.f;
                if (yy >= 0 && yy < NH && xx >= 0 && xx < NW) xv = xp[yy * NW + xx];
                int wi = c * 9 + ky * 3 + kx;
                sq = fmaf(xv, __ldg(wq + wi), sq);
                sk = fmaf(xv, __ldg(wk + wi), sk);
                sv = fmaf(xv, __ldg(wv + wi), sv);
            }
        }
        g_dw[0][t][c][pix] = sq;
        g_dw[1][t][c][pix] = sk;
        g_dw[2][t][c][pix] = sv;
    }
}

// ---------------- kernel 2: pointwise 1x1 (128x128 GEMM) + bias (+scale for q) ----------------
// out[n][pix] = sum_k pw[n][k] * dw[k][pix] + b[n];  dst layout [t*128+n][pix]
__global__ __launch_bounds__(256) void pw_kernel(
    const float* __restrict__ pwq, const float* __restrict__ bq_,
    const float* __restrict__ pwk, const float* __restrict__ bk_,
    const float* __restrict__ pwv, const float* __restrict__ bv_)
{
    __shared__ float Ws[16][128];
    __shared__ float Xs[16][64];
    int tid = threadIdx.x;
    int t = blockIdx.y, proj = blockIdx.z;
    int pix0 = blockIdx.x * 64;
    const float* pw   = (proj == 0) ? pwq : (proj == 1) ? pwk : pwv;
    const float* bias = (proj == 0) ? bq_ : (proj == 1) ? bk_ : bv_;
    const float* dwsrc = &g_dw[proj][t][0][0];
    float* dst = ((proj == 0) ? g_q : (proj == 1) ? g_k : g_v) + t * NC * HW;

    int mlane = tid & 15;   // pixel group (4 pixels)
    int ng = tid >> 4;      // out-channel group (8 channels)
    float acc[4][8];
#pragma unroll
    for (int j = 0; j < 8; j++) {
        float b = bias[ng * 8 + j];
        acc[0][j] = b; acc[1][j] = b; acc[2][j] = b; acc[3][j] = b;
    }
    for (int k0 = 0; k0 < 128; k0 += 16) {
        __syncthreads();
        {   // load Ws[k][n] = pw[n][k0+k]
            int n = tid >> 1, ku = (tid & 1) * 8;
            float4 a = *reinterpret_cast<const float4*>(pw + n * 128 + k0 + ku);
            float4 b2 = *reinterpret_cast<const float4*>(pw + n * 128 + k0 + ku + 4);
            Ws[ku + 0][n] = a.x;  Ws[ku + 1][n] = a.y;  Ws[ku + 2][n] = a.z;  Ws[ku + 3][n] = a.w;
            Ws[ku + 4][n] = b2.x; Ws[ku + 5][n] = b2.y; Ws[ku + 6][n] = b2.z; Ws[ku + 7][n] = b2.w;
        }
        {   // load Xs[k][m] = dw[(t*128+k0+k)][pix0+m]
            int k = tid >> 4, m4 = (tid & 15) * 4;
            float4 x = *reinterpret_cast<const float4*>(dwsrc + (k0 + k) * HW + pix0 + m4);
            *reinterpret_cast<float4*>(&Xs[k][m4]) = x;
        }
        __syncthreads();
#pragma unroll
        for (int k = 0; k < 16; k++) {
            float4 a = *reinterpret_cast<const float4*>(&Xs[k][mlane * 4]);
            float4 b0 = *reinterpret_cast<const float4*>(&Ws[k][ng * 8]);
            float4 b1 = *reinterpret_cast<const float4*>(&Ws[k][ng * 8 + 4]);
            float aa[4] = {a.x, a.y, a.z, a.w};
            float bb[8] = {b0.x, b0.y, b0.z, b0.w, b1.x, b1.y, b1.z, b1.w};
#pragma unroll
            for (int i = 0; i < 4; i++)
#pragma unroll
                for (int j = 0; j < 8; j++)
                    acc[i][j] = fmaf(aa[i], bb[j], acc[i][j]);
        }
    }
    float sc = (proj == 0) ? QSCALE : 1.f;
#pragma unroll
    for (int j = 0; j < 8; j++) {
        int n = ng * 8 + j;
        float4 o = make_float4(acc[0][j] * sc, acc[1][j] * sc, acc[2][j] * sc, acc[3][j] * sc);
        *reinterpret_cast<float4*>(dst + n * HW + pix0 + mlane * 4) = o;
    }
}

// ---------------- kernel 3: non-local attention per (tile, head, frame) ----------------
__global__ __launch_bounds__(256) void attn_kernel()
{
    extern __shared__ float sm[];
    float* ks = sm;                   // [32][529]
    float* vs = sm + 32 * HALO_PIX;   // [32][529]
    int tid = threadIdx.x;
    int tc = (blockIdx.x % 6) * TILE, tr = (blockIdx.x / 6) * TILE;
    int h = blockIdx.y, t = blockIdx.z;
    int base = ((t * HEADS + h) * HD) * HW;
    int br = tr - 4, bc = tc - 4;

    // stage k,v halo tile into smem (layout [d][lp], lp = lr*23+lc)
    for (int idx = tid; idx < HD * HALO_PIX; idx += 256) {
        int d = idx / HALO_PIX, lp = idx - d * HALO_PIX;
        int lr = lp / HALO, lc = lp - lr * HALO;
        int gi = br + lr, gj = bc + lc;
        float kv = 0.f, vv = 0.f;
        if (gi >= 0 && gi < NH && gj >= 0 && gj < NW) {
            int off = base + d * HW + gi * NW + gj;
            kv = g_k[off]; vv = g_v[off];
        }
        ks[idx] = kv; vs[idx] = vv;
    }
    __syncthreads();

    int tx = tid & 15, ty = tid >> 4;
    int gi = tr + ty, gj = tc + tx;

    float qreg[HD];
#pragma unroll
    for (int d = 0; d < HD; d++) qreg[d] = g_q[base + d * HW + gi * NW + gj];

    // reflected local neighbor coordinates
    int lroff[8], lcoff[8];
#pragma unroll
    for (int o = 0; o < 8; o++) {
        int ri = gi + o - 4; ri = (ri < 0) ? -ri : ((ri > 95) ? 190 - ri : ri);
        int rj = gj + o - 4; rj = (rj < 0) ? -rj : ((rj > 95) ? 190 - rj : rj);
        lroff[o] = ri - br;
        lcoff[o] = rj - bc;
    }

    float dist[64];
#pragma unroll
    for (int a = 0; a < 8; a++) {
#pragma unroll
        for (int b = 0; b < 8; b++) {
            int lp = lroff[a] * HALO + lcoff[b];
            float s = 0.f;
#pragma unroll
            for (int d = 0; d < HD; d++) s = fmaf(qreg[d], ks[d * HALO_PIX + lp], s);
            dist[a * 8 + b] = s;
        }
    }

    // exact top-16 set via 16 argmax passes (mark by index -> duplicates handled like jax top_k)
    float tv[16]; int ta[16];
#pragma unroll
    for (int p = 0; p < 16; p++) {
        float m = NEG_HUGE; int am = 0;
#pragma unroll
        for (int j = 0; j < 64; j++) if (dist[j] > m) { m = dist[j]; am = j; }
        tv[p] = m; ta[p] = am;
#pragma unroll
        for (int j = 0; j < 64; j++) if (j == am) dist[j] = NEG_HUGE;
    }

    float mx = tv[0];
    float wsum = 0.f, wgt[16];
#pragma unroll
    for (int p = 0; p < 16; p++) { float e = __expf(tv[p] - mx); wgt[p] = e; wsum += e; }
    float inv = 1.f / wsum;

    float outp[HD];
#pragma unroll
    for (int d = 0; d < HD; d++) outp[d] = 0.f;
#pragma unroll
    for (int p = 0; p < 16; p++) {
        int a = ta[p];
        int ri = gi + (a >> 3) - 4; ri = (ri < 0) ? -ri : ((ri > 95) ? 190 - ri : ri);
        int rj = gj + (a & 7) - 4;  rj = (rj < 0) ? -rj : ((rj > 95) ? 190 - rj : rj);
        int lp = (ri - br) * HALO + (rj - bc);
        float w = wgt[p] * inv;
#pragma unroll
        for (int d = 0; d < HD; d++) outp[d] = fmaf(w, vs[d * HALO_PIX + lp], outp[d]);
    }

    float* op = g_att + (t * HW + gi * NW + gj) * NC + h * HD;
#pragma unroll
    for (int d = 0; d < HD; d += 4)
        *reinterpret_cast<float4*>(op + d) =
            make_float4(outp[d], outp[d + 1], outp[d + 2], outp[d + 3]);
}

// ---------------- kernel 4: final linear proj + transpose to [T][C][H][W] ----------------
__global__ __launch_bounds__(256) void proj_kernel(
    const float* __restrict__ pw, const float* __restrict__ pb,
    float* __restrict__ out)
{
    __shared__ float Ws[16][128];
    __shared__ float Xs[16][64];
    int tid = threadIdx.x;
    int q0 = blockIdx.x * 64;
    int t = q0 / HW, hw0 = q0 - t * HW;
    int mlane = tid & 15, ng = tid >> 4;
    float acc[4][8];
#pragma unroll
    for (int j = 0; j < 8; j++) {
        float b = pb[ng * 8 + j];
        acc[0][j] = b; acc[1][j] = b; acc[2][j] = b; acc[3][j] = b;
    }
    for (int k0 = 0; k0 < 128; k0 += 16) {
        __syncthreads();
        {   // Ws[k][n] = proj_w[n][k0+k]
            int n = tid >> 1, ku = (tid & 1) * 8;
            float4 a = *reinterpret_cast<const float4*>(pw + n * 128 + k0 + ku);
            float4 b2 = *reinterpret_cast<const float4*>(pw + n * 128 + k0 + ku + 4);
            Ws[ku + 0][n] = a.x;  Ws[ku + 1][n] = a.y;  Ws[ku + 2][n] = a.z;  Ws[ku + 3][n] = a.w;
            Ws[ku + 4][n] = b2.x; Ws[ku + 5][n] = b2.y; Ws[ku + 6][n] = b2.z; Ws[ku + 7][n] = b2.w;
        }
        {   // Xs[k][m] = g_att[q0+m][k0+k]
            int m = tid >> 2, ku = (tid & 3) * 4;
            float4 x = *reinterpret_cast<const float4*>(g_att + (q0 + m) * NC + k0 + ku);
            Xs[ku + 0][m] = x.x; Xs[ku + 1][m] = x.y; Xs[ku + 2][m] = x.z; Xs[ku + 3][m] = x.w;
        }
        __syncthreads();
#pragma unroll
        for (int k = 0; k < 16; k++) {
            float4 a = *reinterpret_cast<const float4*>(&Xs[k][mlane * 4]);
            float4 b0 = *reinterpret_cast<const float4*>(&Ws[k][ng * 8]);
            float4 b1 = *reinterpret_cast<const float4*>(&Ws[k][ng * 8 + 4]);
            float aa[4] = {a.x, a.y, a.z, a.w};
            float bb[8] = {b0.x, b0.y, b0.z, b0.w, b1.x, b1.y, b1.z, b1.w};
#pragma unroll
            for (int i = 0; i < 4; i++)
#pragma unroll
                for (int j = 0; j < 8; j++)
                    acc[i][j] = fmaf(aa[i], bb[j], acc[i][j]);
        }
    }
#pragma unroll
    for (int j = 0; j < 8; j++) {
        int n = ng * 8 + j;
        float4 o = make_float4(acc[0][j], acc[1][j], acc[2][j], acc[3][j]);
        *reinterpret_cast<float4*>(out + (t * NC + n) * HW + hw0 + mlane * 4) = o;
    }
}

// ---------------- launch ----------------
extern "C" void kernel_launch(void* const* d_in, const int* in_sizes, int n_in,
                              void* d_out, int out_size)
{
    const float* vid    = (const float*)d_in[0];
    const float* wq_dw  = (const float*)d_in[1];
    const float* wq_pw  = (const float*)d_in[2];
    const float* bq     = (const float*)d_in[3];
    const float* wk_dw  = (const float*)d_in[4];
    const float* wk_pw  = (const float*)d_in[5];
    const float* bk     = (const float*)d_in[6];
    const float* wv_dw  = (const float*)d_in[7];
    const float* wv_pw  = (const float*)d_in[8];
    const float* bv     = (const float*)d_in[9];
    const float* proj_w = (const float*)d_in[10];
    const float* proj_b = (const float*)d_in[11];
    float* out = (float*)d_out;

    const int attn_smem = 2 * HD * HALO_PIX * (int)sizeof(float);  // 135424 B
    cudaFuncSetAttribute(attn_kernel, cudaFuncAttributeMaxDynamicSharedMemorySize, attn_smem);

    dw_kernel<<<dim3(36, 2, 8), 256>>>(vid, wq_dw, wk_dw, wv_dw);
    pw_kernel<<<dim3(144, 2, 3), 256>>>(wq_pw, bq, wk_pw, bk, wv_pw, bv);
    attn_kernel<<<dim3(36, 4, 2), 256, attn_smem>>>();
    proj_kernel<<<dim3(288, 1, 1), 256>>>(proj_w, proj_b, out);
}

// round 2
// speedup vs baseline: 1.2894x; 1.2894x over previous
#include <cuda_runtime.h>
#include <cstdint>

#define NT 2
#define NC 128
#define NH 96
#define NW 96
#define HW 9216        // 96*96
#define NQ 18432       // NT*HW
#define HEADS 4
#define HD 32
#define QSCALE 0.17677669529663687f
#define NEG_HUGE (-3.402823466e38f)

// attention tile: 32 wide x 8 high (warp = one row of 32 queries -> conflict-free LDS)
#define TW 32
#define TH 8
#define HC 39          // TW + 7
#define HR 15          // TH + 7
#define HP 585         // HR*HC

// ---------------- scratch ----------------
__device__ __align__(16) float g_dw[3][NT][NC][HW];          // depthwise results q/k/v
__device__ __align__(16) float g_q[NT * NC * HW];            // [t*128+c][pix]
__device__ __align__(16) float g_k[NT * NC * HW];            // [t*128+c][pix]
__device__ __align__(16) float g_vT[NT * HEADS * HW * HD];   // [t][h][pix][d]  (transposed!)
__device__ __align__(16) float g_att[NQ * NC];               // [q][c]

// ---------------- f32x2 helpers ----------------
__device__ __forceinline__ unsigned long long pk2(float lo, float hi) {
    unsigned long long r;
    asm("mov.b64 %0, {%1, %2};" : "=l"(r) : "f"(lo), "f"(hi));
    return r;
}
__device__ __forceinline__ void upk2(unsigned long long v, float& lo, float& hi) {
    asm("mov.b64 {%0, %1}, %2;" : "=f"(lo), "=f"(hi) : "l"(v));
}
__device__ __forceinline__ void fma2(unsigned long long& d, unsigned long long a, unsigned long long b) {
    asm("fma.rn.f32x2 %0, %1, %2, %0;" : "+l"(d) : "l"(a), "l"(b));
}

// ---------------- kernel 1: depthwise 3x3, zero-pad SAME, 3 projections ----------------
__global__ __launch_bounds__(256) void dw_kernel(
    const float* __restrict__ vid,
    const float* __restrict__ wq, const float* __restrict__ wk,
    const float* __restrict__ wv)
{
    int tx = threadIdx.x & 15, ty = threadIdx.x >> 4;
    int tr = (blockIdx.x / 6) * 16, tc = (blockIdx.x % 6) * 16;
    int t = blockIdx.y, cg = blockIdx.z;
    int gi = tr + ty, gj = tc + tx;
    int pix = gi * NW + gj;
    for (int cc = 0; cc < 16; cc++) {
        int c = cg * 16 + cc;
        const float* xp = vid + (t * NC + c) * HW;
        float sq = 0.f, sk = 0.f, sv = 0.f;
#pragma unroll
        for (int ky = 0; ky < 3; ky++) {
            int yy = gi + ky - 1;
#pragma unroll
            for (int kx = 0; kx < 3; kx++) {
                int xx = gj + kx - 1;
                float xv = 0.f;
                if (yy >= 0 && yy < NH && xx >= 0 && xx < NW) xv = xp[yy * NW + xx];
                int wi = c * 9 + ky * 3 + kx;
                sq = fmaf(xv, __ldg(wq + wi), sq);
                sk = fmaf(xv, __ldg(wk + wi), sk);
                sv = fmaf(xv, __ldg(wv + wi), sv);
            }
        }
        g_dw[0][t][c][pix] = sq;
        g_dw[1][t][c][pix] = sk;
        g_dw[2][t][c][pix] = sv;
    }
}

// ---------------- kernel 2: pointwise 1x1, 128x128x128 GEMM, f32x2 FMA ----------------
// BM=128 pixels, BN=128 channels, BK=16, 256 threads, microtile 4 pix x 16 ch.
__global__ __launch_bounds__(256) void pw_kernel(
    const float* __restrict__ pwq, const float* __restrict__ bq_,
    const float* __restrict__ pwk, const float* __restrict__ bk_,
    const float* __restrict__ pwv, const float* __restrict__ bv_)
{
    __shared__ float Xs[16][128];
    __shared__ float Ws[16][128];
    int tid = threadIdx.x;
    int pix0 = blockIdx.x * 128;
    int t = blockIdx.y, proj = blockIdx.z;
    const float* W    = (proj == 0) ? pwq : (proj == 1) ? pwk : pwv;
    const float* bias = (proj == 0) ? bq_ : (proj == 1) ? bk_ : bv_;
    const float* X = &g_dw[proj][t][0][0];

    int tm = tid & 31;           // pixel group (4 pixels: tm*4..+3)
    int tn = tid >> 5;           // channel group (16 channels: tn*16..+15)
    int n0 = tn * 16;

    unsigned long long acc[4][8];   // [pixel][channel-pair]
#pragma unroll
    for (int c = 0; c < 8; c++) {
        unsigned long long b = pk2(bias[n0 + 2 * c], bias[n0 + 2 * c + 1]);
#pragma unroll
        for (int i = 0; i < 4; i++) acc[i][c] = b;
    }

    for (int k0 = 0; k0 < 128; k0 += 16) {
#pragma unroll
        for (int l = 0; l < 2; l++) {
            int li = tid + l * 256;
            int kk = li >> 5, m4 = (li & 31) * 4;
            *reinterpret_cast<float4*>(&Xs[kk][m4]) =
                *reinterpret_cast<const float4*>(&X[(k0 + kk) * HW + pix0 + m4]);
        }
        {
            int n = tid >> 1, kb = (tid & 1) * 8;
            float4 w0 = *reinterpret_cast<const float4*>(&W[n * 128 + k0 + kb]);
            float4 w1 = *reinterpret_cast<const float4*>(&W[n * 128 + k0 + kb + 4]);
            Ws[kb + 0][n] = w0.x; Ws[kb + 1][n] = w0.y; Ws[kb + 2][n] = w0.z; Ws[kb + 3][n] = w0.w;
            Ws[kb + 4][n] = w1.x; Ws[kb + 5][n] = w1.y; Ws[kb + 6][n] = w1.z; Ws[kb + 7][n] = w1.w;
        }
        __syncthreads();
#pragma unroll
        for (int k = 0; k < 16; k++) {
            float4 a4 = *reinterpret_cast<const float4*>(&Xs[k][tm * 4]);
            unsigned long long ad[4] = {pk2(a4.x, a4.x), pk2(a4.y, a4.y),
                                        pk2(a4.z, a4.z), pk2(a4.w, a4.w)};
#pragma unroll
            for (int c4 = 0; c4 < 4; c4++) {
                ulonglong2 bp = *reinterpret_cast<const ulonglong2*>(&Ws[k][n0 + c4 * 4]);
#pragma unroll
                for (int i = 0; i < 4; i++) {
                    fma2(acc[i][2 * c4 + 0], ad[i], bp.x);
                    fma2(acc[i][2 * c4 + 1], ad[i], bp.y);
                }
            }
        }
        __syncthreads();
    }

    float va[4][16];
#pragma unroll
    for (int i = 0; i < 4; i++)
#pragma unroll
        for (int c = 0; c < 8; c++) upk2(acc[i][c], va[i][2 * c], va[i][2 * c + 1]);

    if (proj == 0) {
#pragma unroll
        for (int i = 0; i < 4; i++)
#pragma unroll
            for (int c2 = 0; c2 < 16; c2++) va[i][c2] *= QSCALE;
    }

    if (proj < 2) {
        float* dst = ((proj == 0) ? g_q : g_k) + t * NC * HW;
#pragma unroll
        for (int c2 = 0; c2 < 16; c2++) {
            float4 o = make_float4(va[0][c2], va[1][c2], va[2][c2], va[3][c2]);
            *reinterpret_cast<float4*>(&dst[(n0 + c2) * HW + pix0 + tm * 4]) = o;
        }
    } else {
        int h = n0 >> 5, dd = n0 & 31;
#pragma unroll
        for (int i = 0; i < 4; i++) {
            int pix = pix0 + tm * 4 + i;
            float* vp = &g_vT[((size_t)(t * HEADS + h) * HW + pix) * HD + dd];
#pragma unroll
            for (int j = 0; j < 4; j++)
                *reinterpret_cast<float4*>(&vp[j * 4]) =
                    make_float4(va[i][4 * j], va[i][4 * j + 1], va[i][4 * j + 2], va[i][4 * j + 3]);
        }
    }
}

// ---------------- kernel 3: non-local attention ----------------
__global__ __launch_bounds__(256, 2) void attn_kernel()
{
    extern __shared__ float ks[];   // [32][585]
    int tid = threadIdx.x;
    int tcx = (blockIdx.x % 3) * TW, trow = (blockIdx.x / 3) * TH;
    int h = blockIdx.y, t = blockIdx.z;
    int base = (t * NC + h * HD) * HW;
    int br = trow - 4, bc = tcx - 4;

    // stage k halo [32 d][15 r][39 c]
    for (int idx = tid; idx < HD * HP; idx += 256) {
        int d = idx / HP, lp = idx - d * HP;
        int lr = lp / HC, lc = lp - lr * HC;
        int gi = br + lr, gj = bc + lc;
        float kv = 0.f;
        if (gi >= 0 && gi < NH && gj >= 0 && gj < NW)
            kv = g_k[base + d * HW + gi * NW + gj];
        ks[idx] = kv;
    }
    __syncthreads();

    int tx = tid & 31, ty = tid >> 5;
    int gi = trow + ty, gj = tcx + tx;

    float qreg[HD];
#pragma unroll
    for (int d = 0; d < HD; d++) qreg[d] = g_q[base + d * HW + gi * NW + gj];

    int lcoff[8];
#pragma unroll
    for (int b = 0; b < 8; b++) {
        int rj = gj + b - 4; rj = (rj < 0) ? -rj : ((rj > 95) ? 190 - rj : rj);
        lcoff[b] = rj - bc;
    }

    float dist[64];
#pragma unroll
    for (int a = 0; a < 8; a++) {
        int ri = gi + a - 4; ri = (ri < 0) ? -ri : ((ri > 95) ? 190 - ri : ri);
        int lrbase = (ri - br) * HC;
#pragma unroll
        for (int b = 0; b < 8; b++) {
            int lp = lrbase + lcoff[b];
            float s = 0.f;
#pragma unroll
            for (int d = 0; d < HD; d++) s = fmaf(qreg[d], ks[d * HP + lp], s);
            dist[a * 8 + b] = s;
        }
    }

    // top-16 with on-the-fly softmax accumulation (unnormalized), v gathered per pick
    const float* vbase = &g_vT[(size_t)(t * HEADS + h) * HW * HD];
    unsigned long long acc2[16];
#pragma unroll
    for (int c = 0; c < 16; c++) acc2[c] = 0ull;
    float mx = 0.f, wsum = 0.f;

#pragma unroll 1
    for (int p = 0; p < 16; p++) {
        // 8 independent serial chains of 8, then tree combine (low index wins ties)
        float gv[8]; int gidx[8];
#pragma unroll
        for (int g = 0; g < 8; g++) {
            float mv = dist[g * 8]; int mi = g * 8;
#pragma unroll
            for (int j = 1; j < 8; j++) {
                float dv = dist[g * 8 + j];
                if (dv > mv) { mv = dv; mi = g * 8 + j; }
            }
            gv[g] = mv; gidx[g] = mi;
        }
        float v4a = gv[0]; int i4a = gidx[0];
        if (gv[1] > v4a) { v4a = gv[1]; i4a = gidx[1]; }
        float v4b = gv[2]; int i4b = gidx[2];
        if (gv[3] > v4b) { v4b = gv[3]; i4b = gidx[3]; }
        float v4c = gv[4]; int i4c = gidx[4];
        if (gv[5] > v4c) { v4c = gv[5]; i4c = gidx[5]; }
        float v4d = gv[6]; int i4d = gidx[6];
        if (gv[7] > v4d) { v4d = gv[7]; i4d = gidx[7]; }
        if (v4b > v4a) { v4a = v4b; i4a = i4b; }
        if (v4d > v4c) { v4c = v4d; i4c = i4d; }
        float m = v4a; int am = i4a;
        if (v4c > m) { m = v4c; am = i4c; }

#pragma unroll
        for (int j = 0; j < 64; j++) if (j == am) dist[j] = NEG_HUGE;

        if (p == 0) mx = m;
        float e = __expf(m - mx);
        wsum += e;
        unsigned long long ed = pk2(e, e);

        int a = am >> 3, b = am & 7;
        int ri = gi + a - 4; ri = (ri < 0) ? -ri : ((ri > 95) ? 190 - ri : ri);
        int rj = gj + b - 4; rj = (rj < 0) ? -rj : ((rj > 95) ? 190 - rj : rj);
        const unsigned long long* vp =
            reinterpret_cast<const unsigned long long*>(vbase + (ri * NW + rj) * HD);
#pragma unroll
        for (int c = 0; c < 16; c++) fma2(acc2[c], ed, __ldg(vp + c));
    }

    float inv = 1.f / wsum;
    float* op = g_att + ((size_t)(t * HW + gi * NW + gj)) * NC + h * HD;
#pragma unroll
    for (int c = 0; c < 8; c++) {
        float l0, h0, l1, h1;
        upk2(acc2[2 * c], l0, h0);
        upk2(acc2[2 * c + 1], l1, h1);
        *reinterpret_cast<float4*>(op + c * 4) =
            make_float4(l0 * inv, h0 * inv, l1 * inv, h1 * inv);
    }
}

// ---------------- kernel 4: final projection GEMM ----------------
__global__ __launch_bounds__(256) void proj_kernel(
    const float* __restrict__ W, const float* __restrict__ pb,
    float* __restrict__ out)
{
    __shared__ float Xs[16][128];
    __shared__ float Ws[16][128];
    int tid = threadIdx.x;
    int q0 = blockIdx.x * 128;
    int t = q0 / HW, hw0 = q0 - t * HW;
    int tm = tid & 31, tn = tid >> 5;
    int n0 = tn * 16;

    unsigned long long acc[4][8];
#pragma unroll
    for (int c = 0; c < 8; c++) {
        unsigned long long b = pk2(pb[n0 + 2 * c], pb[n0 + 2 * c + 1]);
#pragma unroll
        for (int i = 0; i < 4; i++) acc[i][c] = b;
    }

    for (int k0 = 0; k0 < 128; k0 += 16) {
        {   // transposed load: Xs[k][m] = g_att[q0+m][k0+k]
            int m = tid >> 1, kb = (tid & 1) * 8;
            float4 x0 = *reinterpret_cast<const float4*>(&g_att[(size_t)(q0 + m) * NC + k0 + kb]);
            float4 x1 = *reinterpret_cast<const float4*>(&g_att[(size_t)(q0 + m) * NC + k0 + kb + 4]);
            Xs[kb + 0][m] = x0.x; Xs[kb + 1][m] = x0.y; Xs[kb + 2][m] = x0.z; Xs[kb + 3][m] = x0.w;
            Xs[kb + 4][m] = x1.x; Xs[kb + 5][m] = x1.y; Xs[kb + 6][m] = x1.z; Xs[kb + 7][m] = x1.w;
        }
        {
            int n = tid >> 1, kb = (tid & 1) * 8;
            float4 w0 = *reinterpret_cast<const float4*>(&W[n * 128 + k0 + kb]);
            float4 w1 = *reinterpret_cast<const float4*>(&W[n * 128 + k0 + kb + 4]);
            Ws[kb + 0][n] = w0.x; Ws[kb + 1][n] = w0.y; Ws[kb + 2][n] = w0.z; Ws[kb + 3][n] = w0.w;
            Ws[kb + 4][n] = w1.x; Ws[kb + 5][n] = w1.y; Ws[kb + 6][n] = w1.z; Ws[kb + 7][n] = w1.w;
        }
        __syncthreads();
#pragma unroll
        for (int k = 0; k < 16; k++) {
            float4 a4 = *reinterpret_cast<const float4*>(&Xs[k][tm * 4]);
            unsigned long long ad[4] = {pk2(a4.x, a4.x), pk2(a4.y, a4.y),
                                        pk2(a4.z, a4.z), pk2(a4.w, a4.w)};
#pragma unroll
            for (int c4 = 0; c4 < 4; c4++) {
                ulonglong2 bp = *reinterpret_cast<const ulonglong2*>(&Ws[k][n0 + c4 * 4]);
#pragma unroll
                for (int i = 0; i < 4; i++) {
                    fma2(acc[i][2 * c4 + 0], ad[i], bp.x);
                    fma2(acc[i][2 * c4 + 1], ad[i], bp.y);
                }
            }
        }
        __syncthreads();
    }

    float va[4][16];
#pragma unroll
    for (int i = 0; i < 4; i++)
#pragma unroll
        for (int c = 0; c < 8; c++) upk2(acc[i][c], va[i][2 * c], va[i][2 * c + 1]);

#pragma unroll
    for (int c2 = 0; c2 < 16; c2++) {
        float4 o = make_float4(va[0][c2], va[1][c2], va[2][c2], va[3][c2]);
        *reinterpret_cast<float4*>(&out[(size_t)(t * NC + n0 + c2) * HW + hw0 + tm * 4]) = o;
    }
}

// ---------------- launch ----------------
extern "C" void kernel_launch(void* const* d_in, const int* in_sizes, int n_in,
                              void* d_out, int out_size)
{
    const float* vid    = (const float*)d_in[0];
    const float* wq_dw  = (const float*)d_in[1];
    const float* wq_pw  = (const float*)d_in[2];
    const float* bq     = (const float*)d_in[3];
    const float* wk_dw  = (const float*)d_in[4];
    const float* wk_pw  = (const float*)d_in[5];
    const float* bk     = (const float*)d_in[6];
    const float* wv_dw  = (const float*)d_in[7];
    const float* wv_pw  = (const float*)d_in[8];
    const float* bv     = (const float*)d_in[9];
    const float* proj_w = (const float*)d_in[10];
    const float* proj_b = (const float*)d_in[11];
    float* out = (float*)d_out;

    const int attn_smem = HD * HP * (int)sizeof(float);  // 74880 B
    cudaFuncSetAttribute(attn_kernel, cudaFuncAttributeMaxDynamicSharedMemorySize, attn_smem);

    dw_kernel<<<dim3(36, 2, 8), 256>>>(vid, wq_dw, wk_dw, wv_dw);
    pw_kernel<<<dim3(72, 2, 3), 256>>>(wq_pw, bq, wk_pw, bk, wv_pw, bv);
    attn_kernel<<<dim3(36, 4, 2), 256, attn_smem>>>();
    proj_kernel<<<dim3(144, 1, 1), 256>>>(proj_w, proj_b, out);
}

// round 3
// speedup vs baseline: 1.4742x; 1.1433x over previous
#include <cuda_runtime.h>
#include <cstdint>

#define NT 2
#define NC 128
#define NH 96
#define NW 96
#define HW 9216        // 96*96
#define NQ 18432       // NT*HW
#define HEADS 4
#define HD 32
#define QSCALE 0.17677669529663687f

// attention tile: 32 wide x 8 high
#define TW 32
#define TH 8
#define HC 39          // TW + 7
#define HR 15          // TH + 7
#define HP 585         // HR*HC

typedef unsigned long long ull;

// ---------------- scratch ----------------
__device__ __align__(16) float g_dw[3][NT][NC][HW];          // depthwise results q/k/v
__device__ __align__(16) float g_q[NT * NC * HW];            // [t*128+c][pix]
__device__ __align__(16) float g_k[NT * NC * HW];            // [t*128+c][pix]
__device__ __align__(16) float g_vT[NT * HEADS * HW * HD];   // [t][h][pix][d]
__device__ __align__(16) float g_att[NQ * NC];               // [q][c]

// ---------------- f32x2 helpers ----------------
__device__ __forceinline__ ull pk2(float lo, float hi) {
    ull r;
    asm("mov.b64 %0, {%1, %2};" : "=l"(r) : "f"(lo), "f"(hi));
    return r;
}
__device__ __forceinline__ void upk2(ull v, float& lo, float& hi) {
    asm("mov.b64 {%0, %1}, %2;" : "=f"(lo), "=f"(hi) : "l"(v));
}
__device__ __forceinline__ void fma2(ull& d, ull a, ull b) {
    asm("fma.rn.f32x2 %0, %1, %2, %0;" : "+l"(d) : "l"(a), "l"(b));
}
__device__ __forceinline__ int refl(int i) {
    i = (i < 0) ? -i : i;
    return (i > 95) ? 190 - i : i;
}

// ---------------- kernel 1: depthwise 3x3, zero-pad SAME ----------------
// block 256 = 32x8, each thread 4 vertical pixels, 8 channels; grid (9, 2, 16)
__global__ __launch_bounds__(256) void dw_kernel(
    const float* __restrict__ vid,
    const float* __restrict__ wq, const float* __restrict__ wk,
    const float* __restrict__ wv)
{
    int tid = threadIdx.x;
    int tx = tid & 31, ty = tid >> 5;
    int tilec = (blockIdx.x % 3) * 32, tiler = (blockIdx.x / 3) * 32;
    int t = blockIdx.y, cg = blockIdx.z;
    int gj = tilec + tx;
    int r0 = tiler + ty * 4;

    for (int cc = 0; cc < 8; cc++) {
        int c = cg * 8 + cc;
        const float* xp = vid + (t * NC + c) * HW;
        float x[6][3];
#pragma unroll
        for (int rr = 0; rr < 6; rr++) {
            int yy = r0 + rr - 1;
            bool yok = (yy >= 0 && yy < NH);
#pragma unroll
            for (int jj = 0; jj < 3; jj++) {
                int xxc = gj + jj - 1;
                x[rr][jj] = (yok && xxc >= 0 && xxc < NW) ? xp[yy * NW + xxc] : 0.f;
            }
        }
        const float* wqc = wq + c * 9;
        const float* wkc = wk + c * 9;
        const float* wvc = wv + c * 9;
        float wqr[9], wkr[9], wvr[9];
#pragma unroll
        for (int i = 0; i < 9; i++) { wqr[i] = wqc[i]; wkr[i] = wkc[i]; wvr[i] = wvc[i]; }
#pragma unroll
        for (int p = 0; p < 4; p++) {
            float sq = 0.f, sk = 0.f, sv = 0.f;
#pragma unroll
            for (int ky = 0; ky < 3; ky++)
#pragma unroll
                for (int kx = 0; kx < 3; kx++) {
                    float xv = x[p + ky][kx];
                    sq = fmaf(xv, wqr[ky * 3 + kx], sq);
                    sk = fmaf(xv, wkr[ky * 3 + kx], sk);
                    sv = fmaf(xv, wvr[ky * 3 + kx], sv);
                }
            int pix = (r0 + p) * NW + gj;
            g_dw[0][t][c][pix] = sq;
            g_dw[1][t][c][pix] = sk;
            g_dw[2][t][c][pix] = sv;
        }
    }
}

// ---------------- kernel 2: pointwise 1x1 GEMM, BM=64, f32x2 ----------------
__global__ __launch_bounds__(256) void pw_kernel(
    const float* __restrict__ pwq, const float* __restrict__ bq_,
    const float* __restrict__ pwk, const float* __restrict__ bk_,
    const float* __restrict__ pwv, const float* __restrict__ bv_)
{
    __shared__ float Xs[16][64];
    __shared__ float Ws[16][128];
    int tid = threadIdx.x;
    int pix0 = blockIdx.x * 64;
    int t = blockIdx.y, proj = blockIdx.z;
    const float* W    = (proj == 0) ? pwq : (proj == 1) ? pwk : pwv;
    const float* bias = (proj == 0) ? bq_ : (proj == 1) ? bk_ : bv_;
    const float* X = &g_dw[proj][t][0][0];

    int tm = tid & 31;           // pixel pair (2 pixels)
    int tn = tid >> 5;           // channel group of 16
    int n0 = tn * 16;

    ull acc[2][8];
#pragma unroll
    for (int c = 0; c < 8; c++) {
        ull b = pk2(bias[n0 + 2 * c], bias[n0 + 2 * c + 1]);
        acc[0][c] = b; acc[1][c] = b;
    }

    for (int k0 = 0; k0 < 128; k0 += 16) {
        {   // Xs[16][64]: each thread one float4
            int kk = tid >> 4, m4 = (tid & 15) * 4;
            *reinterpret_cast<float4*>(&Xs[kk][m4]) =
                *reinterpret_cast<const float4*>(&X[(k0 + kk) * HW + pix0 + m4]);
        }
        {   // Ws[16][128]
            int n = tid >> 1, kb = (tid & 1) * 8;
            float4 w0 = *reinterpret_cast<const float4*>(&W[n * 128 + k0 + kb]);
            float4 w1 = *reinterpret_cast<const float4*>(&W[n * 128 + k0 + kb + 4]);
            Ws[kb + 0][n] = w0.x; Ws[kb + 1][n] = w0.y; Ws[kb + 2][n] = w0.z; Ws[kb + 3][n] = w0.w;
            Ws[kb + 4][n] = w1.x; Ws[kb + 5][n] = w1.y; Ws[kb + 6][n] = w1.z; Ws[kb + 7][n] = w1.w;
        }
        __syncthreads();
#pragma unroll
        for (int k = 0; k < 16; k++) {
            float2 a2 = *reinterpret_cast<const float2*>(&Xs[k][tm * 2]);
            ull ad0 = pk2(a2.x, a2.x), ad1 = pk2(a2.y, a2.y);
#pragma unroll
            for (int c4 = 0; c4 < 4; c4++) {
                ulonglong2 bp = *reinterpret_cast<const ulonglong2*>(&Ws[k][n0 + c4 * 4]);
                fma2(acc[0][2 * c4 + 0], ad0, bp.x);
                fma2(acc[0][2 * c4 + 1], ad0, bp.y);
                fma2(acc[1][2 * c4 + 0], ad1, bp.x);
                fma2(acc[1][2 * c4 + 1], ad1, bp.y);
            }
        }
        __syncthreads();
    }

    float va[2][16];
#pragma unroll
    for (int i = 0; i < 2; i++)
#pragma unroll
        for (int c = 0; c < 8; c++) upk2(acc[i][c], va[i][2 * c], va[i][2 * c + 1]);

    if (proj == 0) {
#pragma unroll
        for (int i = 0; i < 2; i++)
#pragma unroll
            for (int c2 = 0; c2 < 16; c2++) va[i][c2] *= QSCALE;
    }

    if (proj < 2) {
        float* dst = ((proj == 0) ? g_q : g_k) + t * NC * HW;
#pragma unroll
        for (int c2 = 0; c2 < 16; c2++)
            *reinterpret_cast<float2*>(&dst[(n0 + c2) * HW + pix0 + tm * 2]) =
                make_float2(va[0][c2], va[1][c2]);
    } else {
        int h = n0 >> 5, dd = n0 & 31;
#pragma unroll
        for (int i = 0; i < 2; i++) {
            int pix = pix0 + tm * 2 + i;
            float* vp = &g_vT[((size_t)(t * HEADS + h) * HW + pix) * HD + dd];
#pragma unroll
            for (int j = 0; j < 4; j++)
                *reinterpret_cast<float4*>(&vp[j * 4]) =
                    make_float4(va[i][4 * j], va[i][4 * j + 1], va[i][4 * j + 2], va[i][4 * j + 3]);
        }
    }
}

// ---------------- kernel 3: non-local attention ----------------
// smem: reflected k halo in d-quad layout: float4 index = d4*HP + lp
#define CE(i, j) do { unsigned _a = key[i], _b = key[j]; \
    key[i] = (_a > _b) ? _a : _b; key[j] = (_a > _b) ? _b : _a; } while (0)

#define SORT8(o) do { \
    CE(o+0,o+1); CE(o+2,o+3); CE(o+4,o+5); CE(o+6,o+7); \
    CE(o+0,o+2); CE(o+1,o+3); CE(o+4,o+6); CE(o+5,o+7); \
    CE(o+1,o+2); CE(o+5,o+6); \
    CE(o+0,o+4); CE(o+1,o+5); CE(o+2,o+6); CE(o+3,o+7); \
    CE(o+2,o+4); CE(o+3,o+5); \
    CE(o+1,o+2); CE(o+3,o+4); CE(o+5,o+6); } while (0)

#define BM8(o) do { \
    CE(o+0,o+4); CE(o+1,o+5); CE(o+2,o+6); CE(o+3,o+7); \
    CE(o+0,o+2); CE(o+1,o+3); CE(o+4,o+6); CE(o+5,o+7); \
    CE(o+0,o+1); CE(o+2,o+3); CE(o+4,o+5); CE(o+6,o+7); } while (0)

#define MERGE16(o) do { \
    CE(o+0,o+15); CE(o+1,o+14); CE(o+2,o+13); CE(o+3,o+12); \
    CE(o+4,o+11); CE(o+5,o+10); CE(o+6,o+9);  CE(o+7,o+8); \
    BM8(o); BM8(o+8); } while (0)

#define SORTB16(o) do { \
    CE(o+0,o+8);  CE(o+1,o+9);  CE(o+2,o+10); CE(o+3,o+11); \
    CE(o+4,o+12); CE(o+5,o+13); CE(o+6,o+14); CE(o+7,o+15); \
    BM8(o); BM8(o+8); } while (0)

__global__ __launch_bounds__(256, 2) void attn_kernel()
{
    extern __shared__ float ks[];
    const int tid = threadIdx.x;
    const int tx = tid & 31, ty = tid >> 5;
    const int tcx = (blockIdx.x % 3) * TW, trow = (blockIdx.x / 3) * TH;
    const int h = blockIdx.y, t = blockIdx.z;
    const int base = (t * NC + h * HD) * HW;
    const int br = trow - 4, bc = tcx - 4;

    // stage reflected k halo, d-quads interleaved
    for (int idx = tid; idx < 8 * HP; idx += 256) {
        int d4 = idx / HP, lp = idx - d4 * HP;
        int lr = lp / HC, lc = lp - lr * HC;
        int ri = refl(br + lr), rj = refl(bc + lc);
        const float* gp = g_k + base + (d4 * 4) * HW + ri * NW + rj;
        reinterpret_cast<float4*>(ks)[idx] =
            make_float4(gp[0], gp[HW], gp[2 * HW], gp[3 * HW]);
    }
    __syncthreads();

    const int gi = trow + ty, gj = tcx + tx;
    const int pix = gi * NW + gj;

    ull q2[16];
#pragma unroll
    for (int d2 = 0; d2 < 16; d2++)
        q2[d2] = pk2(g_q[base + (2 * d2) * HW + pix], g_q[base + (2 * d2 + 1) * HW + pix]);

    unsigned key[64];
#pragma unroll
    for (int a = 0; a < 8; a++) {
#pragma unroll
        for (int b = 0; b < 8; b++) {
            int lp = (ty + a) * HC + (tx + b);
            const float4* kp = reinterpret_cast<const float4*>(ks) + lp;
            ull s0 = 0ull, s1 = 0ull;
#pragma unroll
            for (int d4 = 0; d4 < 8; d4++) {
                float4 kv = kp[d4 * HP];
                fma2(s0, q2[2 * d4],     pk2(kv.x, kv.y));
                fma2(s1, q2[2 * d4 + 1], pk2(kv.z, kv.w));
            }
            float x0, x1, y0, y1;
            upk2(s0, x0, x1); upk2(s1, y0, y1);
            float s = (x0 + y0) + (x1 + y1);
            unsigned u = __float_as_uint(s);
            unsigned kk = (u & 0x80000000u) ? ~u : (u | 0x80000000u);
            key[a * 8 + b] = (kk & 0xFFFFFFC0u) | (unsigned)(a * 8 + b);
        }
    }

    // sort 8 groups of 8 descending
    SORT8(0); SORT8(8); SORT8(16); SORT8(24);
    SORT8(32); SORT8(40); SORT8(48); SORT8(56);
    // merge into 4 sorted-16
    MERGE16(0); MERGE16(16); MERGE16(32); MERGE16(48);
    // top-16 of (0,1) -> key[0..15] sorted
#pragma unroll
    for (int i = 0; i < 16; i++) { unsigned b2 = key[31 - i]; if (b2 > key[i]) key[i] = b2; }
    SORTB16(0);
    // top-16 of (2,3) -> key[32..47] sorted
#pragma unroll
    for (int i = 0; i < 16; i++) { unsigned b2 = key[63 - i]; if (b2 > key[32 + i]) key[32 + i] = b2; }
    SORTB16(32);
    unsigned mxkey = (key[0] > key[32]) ? key[0] : key[32];
    // final top-16 (unsorted ok)
#pragma unroll
    for (int i = 0; i < 16; i++) { unsigned b2 = key[47 - i]; if (b2 > key[i]) key[i] = b2; }

    unsigned mu = (mxkey & 0x80000000u) ? (mxkey ^ 0x80000000u) : ~mxkey;
    float mxv = __uint_as_float(mu);

    const float* vbase = g_vT + (size_t)(t * HEADS + h) * HW * HD;
    ull acc2[16];
#pragma unroll
    for (int c = 0; c < 16; c++) acc2[c] = 0ull;
    float wsum = 0.f;

#pragma unroll
    for (int p = 0; p < 16; p++) {
        unsigned kk = key[p];
        int ci = kk & 63;
        unsigned u = (kk & 0x80000000u) ? (kk ^ 0x80000000u) : ~kk;
        float f = __uint_as_float(u);
        float e = __expf(f - mxv);
        wsum += e;
        int ri = refl(br + ty + (ci >> 3));
        int rj = refl(bc + tx + (ci & 7));
        const ull* vp = reinterpret_cast<const ull*>(vbase + (ri * NW + rj) * HD);
        ull e2 = pk2(e, e);
#pragma unroll
        for (int c = 0; c < 16; c++) fma2(acc2[c], e2, __ldg(vp + c));
    }

    float inv = 1.f / wsum;
    float* op = g_att + ((size_t)(t * HW + pix)) * NC + h * HD;
#pragma unroll
    for (int c = 0; c < 8; c++) {
        float l0, h0, l1, h1;
        upk2(acc2[2 * c], l0, h0);
        upk2(acc2[2 * c + 1], l1, h1);
        *reinterpret_cast<float4*>(op + c * 4) =
            make_float4(l0 * inv, h0 * inv, l1 * inv, h1 * inv);
    }
}

// ---------------- kernel 4: final projection GEMM, BM=64 ----------------
__global__ __launch_bounds__(256) void proj_kernel(
    const float* __restrict__ W, const float* __restrict__ pb,
    float* __restrict__ out)
{
    __shared__ float Xs[16][64];
    __shared__ float Ws[16][128];
    int tid = threadIdx.x;
    int q0 = blockIdx.x * 64;
    int t = q0 / HW, hw0 = q0 - t * HW;
    int tm = tid & 31, tn = tid >> 5;
    int n0 = tn * 16;

    ull acc[2][8];
#pragma unroll
    for (int c = 0; c < 8; c++) {
        ull b = pk2(pb[n0 + 2 * c], pb[n0 + 2 * c + 1]);
        acc[0][c] = b; acc[1][c] = b;
    }

    for (int k0 = 0; k0 < 128; k0 += 16) {
        {   // transposed: Xs[k][m] = g_att[q0+m][k0+k]
            int m = tid >> 2, kb = (tid & 3) * 4;
            float4 x = *reinterpret_cast<const float4*>(&g_att[(size_t)(q0 + m) * NC + k0 + kb]);
            Xs[kb + 0][m] = x.x; Xs[kb + 1][m] = x.y; Xs[kb + 2][m] = x.z; Xs[kb + 3][m] = x.w;
        }
        {
            int n = tid >> 1, kb = (tid & 1) * 8;
            float4 w0 = *reinterpret_cast<const float4*>(&W[n * 128 + k0 + kb]);
            float4 w1 = *reinterpret_cast<const float4*>(&W[n * 128 + k0 + kb + 4]);
            Ws[kb + 0][n] = w0.x; Ws[kb + 1][n] = w0.y; Ws[kb + 2][n] = w0.z; Ws[kb + 3][n] = w0.w;
            Ws[kb + 4][n] = w1.x; Ws[kb + 5][n] = w1.y; Ws[kb + 6][n] = w1.z; Ws[kb + 7][n] = w1.w;
        }
        __syncthreads();
#pragma unroll
        for (int k = 0; k < 16; k++) {
            float2 a2 = *reinterpret_cast<const float2*>(&Xs[k][tm * 2]);
            ull ad0 = pk2(a2.x, a2.x), ad1 = pk2(a2.y, a2.y);
#pragma unroll
            for (int c4 = 0; c4 < 4; c4++) {
                ulonglong2 bp = *reinterpret_cast<const ulonglong2*>(&Ws[k][n0 + c4 * 4]);
                fma2(acc[0][2 * c4 + 0], ad0, bp.x);
                fma2(acc[0][2 * c4 + 1], ad0, bp.y);
                fma2(acc[1][2 * c4 + 0], ad1, bp.x);
                fma2(acc[1][2 * c4 + 1], ad1, bp.y);
            }
        }
        __syncthreads();
    }

    float va[2][16];
#pragma unroll
    for (int i = 0; i < 2; i++)
#pragma unroll
        for (int c = 0; c < 8; c++) upk2(acc[i][c], va[i][2 * c], va[i][2 * c + 1]);

#pragma unroll
    for (int c2 = 0; c2 < 16; c2++)
        *reinterpret_cast<float2*>(&out[(size_t)(t * NC + n0 + c2) * HW + hw0 + tm * 2]) =
            make_float2(va[0][c2], va[1][c2]);
}

// ---------------- launch ----------------
extern "C" void kernel_launch(void* const* d_in, const int* in_sizes, int n_in,
                              void* d_out, int out_size)
{
    const float* vid    = (const float*)d_in[0];
    const float* wq_dw  = (const float*)d_in[1];
    const float* wq_pw  = (const float*)d_in[2];
    const float* bq     = (const float*)d_in[3];
    const float* wk_dw  = (const float*)d_in[4];
    const float* wk_pw  = (const float*)d_in[5];
    const float* bk     = (const float*)d_in[6];
    const float* wv_dw  = (const float*)d_in[7];
    const float* wv_pw  = (const float*)d_in[8];
    const float* bv     = (const float*)d_in[9];
    const float* proj_w = (const float*)d_in[10];
    const float* proj_b = (const float*)d_in[11];
    float* out = (float*)d_out;

    const int attn_smem = HD * HP * (int)sizeof(float);  // 74880 B
    cudaFuncSetAttribute(attn_kernel, cudaFuncAttributeMaxDynamicSharedMemorySize, attn_smem);

    dw_kernel<<<dim3(9, 2, 16), 256>>>(vid, wq_dw, wk_dw, wv_dw);
    pw_kernel<<<dim3(144, 2, 3), 256>>>(wq_pw, bq, wk_pw, bk, wv_pw, bv);
    attn_kernel<<<dim3(36, 4, 2), 256, attn_smem>>>();
    proj_kernel<<<dim3(288, 1, 1), 256>>>(proj_w, proj_b, out);
}

// round 4
// speedup vs baseline: 1.6088x; 1.0913x over previous
#include <cuda_runtime.h>
#include <cstdint>

#define NT 2
#define NC 128
#define NH 96
#define NW 96
#define HW 9216        // 96*96
#define NQ 18432       // NT*HW
#define HEADS 4
#define HD 32
#define QSCALE 0.17677669529663687f

// attention tile: 32 wide x 8 high
#define TW 32
#define TH 8
#define HC 39          // TW + 7
#define HR 15          // TH + 7
#define HP 585         // HR*HC

typedef unsigned long long ull;

// ---------------- scratch ----------------
__device__ __align__(16) float g_dw[3][NT][NC][HW];          // depthwise results q/k/v
__device__ __align__(16) float g_q[NT * NC * HW];            // [t*128+c][pix]
__device__ __align__(16) float g_k[NT * NC * HW];            // [t*128+c][pix]
__device__ __align__(16) float g_vT[NT * HEADS * HW * HD];   // [t][h][pix][d]
__device__ __align__(16) float g_att[NC * NQ];               // [c][q]  channel-major
__device__ __align__(16) float g_WT[4][NC][NC];              // transposed weights [k][n]

// ---------------- f32x2 helpers ----------------
__device__ __forceinline__ ull pk2(float lo, float hi) {
    ull r;
    asm("mov.b64 %0, {%1, %2};" : "=l"(r) : "f"(lo), "f"(hi));
    return r;
}
__device__ __forceinline__ void upk2(ull v, float& lo, float& hi) {
    asm("mov.b64 {%0, %1}, %2;" : "=f"(lo), "=f"(hi) : "l"(v));
}
__device__ __forceinline__ void fma2(ull& d, ull a, ull b) {
    asm("fma.rn.f32x2 %0, %1, %2, %0;" : "+l"(d) : "l"(a), "l"(b));
}
__device__ __forceinline__ int refl(int i) {
    i = (i < 0) ? -i : i;
    return (i > 95) ? 190 - i : i;
}

// ---------------- kernel 0: transpose weights into [k][n] ----------------
__global__ __launch_bounds__(256) void wt_kernel(
    const float* __restrict__ w0, const float* __restrict__ w1,
    const float* __restrict__ w2, const float* __restrict__ w3)
{
    __shared__ float tile[32][33];
    const float* srcs[4] = {w0, w1, w2, w3};
    int m = blockIdx.y;
    const float* W = srcs[m];
    int tr = blockIdx.x >> 2, tc = blockIdx.x & 3;   // 4x4 tiles of 32x32
    int tx = threadIdx.x & 31, ty = threadIdx.x >> 5;
#pragma unroll
    for (int i = 0; i < 4; i++)
        tile[ty * 4 + i][tx] = W[(tr * 32 + ty * 4 + i) * NC + tc * 32 + tx];
    __syncthreads();
#pragma unroll
    for (int i = 0; i < 4; i++)
        g_WT[m][tc * 32 + ty * 4 + i][tr * 32 + tx] = tile[tx][ty * 4 + i];
}

// ---------------- kernel 1: depthwise 3x3, zero-pad SAME ----------------
__global__ __launch_bounds__(256) void dw_kernel(
    const float* __restrict__ vid,
    const float* __restrict__ wq, const float* __restrict__ wk,
    const float* __restrict__ wv)
{
    int tid = threadIdx.x;
    int tx = tid & 31, ty = tid >> 5;
    int tilec = (blockIdx.x % 3) * 32, tiler = (blockIdx.x / 3) * 32;
    int t = blockIdx.y, cg = blockIdx.z;
    int gj = tilec + tx;
    int r0 = tiler + ty * 4;

    for (int cc = 0; cc < 8; cc++) {
        int c = cg * 8 + cc;
        const float* xp = vid + (t * NC + c) * HW;
        float x[6][3];
#pragma unroll
        for (int rr = 0; rr < 6; rr++) {
            int yy = r0 + rr - 1;
            bool yok = (yy >= 0 && yy < NH);
#pragma unroll
            for (int jj = 0; jj < 3; jj++) {
                int xxc = gj + jj - 1;
                x[rr][jj] = (yok && xxc >= 0 && xxc < NW) ? xp[yy * NW + xxc] : 0.f;
            }
        }
        const float* wqc = wq + c * 9;
        const float* wkc = wk + c * 9;
        const float* wvc = wv + c * 9;
        float wqr[9], wkr[9], wvr[9];
#pragma unroll
        for (int i = 0; i < 9; i++) { wqr[i] = wqc[i]; wkr[i] = wkc[i]; wvr[i] = wvc[i]; }
#pragma unroll
        for (int p = 0; p < 4; p++) {
            float sq = 0.f, sk = 0.f, sv = 0.f;
#pragma unroll
            for (int ky = 0; ky < 3; ky++)
#pragma unroll
                for (int kx = 0; kx < 3; kx++) {
                    float xv = x[p + ky][kx];
                    sq = fmaf(xv, wqr[ky * 3 + kx], sq);
                    sk = fmaf(xv, wkr[ky * 3 + kx], sk);
                    sv = fmaf(xv, wvr[ky * 3 + kx], sv);
                }
            int pix = (r0 + p) * NW + gj;
            g_dw[0][t][c][pix] = sq;
            g_dw[1][t][c][pix] = sk;
            g_dw[2][t][c][pix] = sv;
        }
    }
}

// ================= GEMM core =================
// dyn smem: Ws[128][128] (64KB) then Xs[2][16][128] (16KB)
// 256 threads, BM=128 pixels, microtile 4 pix x 16 ch, X double-buffered.
struct GemmOut { float va[4][16]; };

__device__ __forceinline__ void gemm_core(
    const float* __restrict__ WT, const float* __restrict__ bias,
    const float* __restrict__ X, int xstride, int x0,
    float (&va)[4][16])
{
    extern __shared__ float sm[];
    float* Ws = sm;                 // [128][128]
    float* Xs = sm + NC * NC;       // [2][16][128]
    const int tid = threadIdx.x;
    const int tm = tid & 31, tn = tid >> 5;
    const int n0 = tn * 16;

    // load whole W (already [k][n]) : 4096 float4 / 256 thr = 16 each
#pragma unroll
    for (int i = 0; i < 16; i++)
        reinterpret_cast<float4*>(Ws)[tid + i * 256] =
            reinterpret_cast<const float4*>(WT)[tid + i * 256];

    // load X chunk 0: 512 float4 / 256 thr = 2 each; float4 f: k=f>>5, m4=f&31
    {
        int f0 = tid * 2;
#pragma unroll
        for (int j = 0; j < 2; j++) {
            int f = f0 + j, kk = f >> 5, m4 = f & 31;
            reinterpret_cast<float4*>(Xs)[f] =
                *reinterpret_cast<const float4*>(&X[(size_t)kk * xstride + x0 + m4 * 4]);
        }
    }
    __syncthreads();

    ull acc[4][8];
#pragma unroll
    for (int c = 0; c < 8; c++) {
        ull b = pk2(bias[n0 + 2 * c], bias[n0 + 2 * c + 1]);
#pragma unroll
        for (int i = 0; i < 4; i++) acc[i][c] = b;
    }

#pragma unroll 1
    for (int kc = 0; kc < 8; kc++) {
        float4 pre[2];
        if (kc < 7) {
            int f0 = tid * 2;
#pragma unroll
            for (int j = 0; j < 2; j++) {
                int f = f0 + j, kk = (kc + 1) * 16 + (f >> 5), m4 = f & 31;
                pre[j] = *reinterpret_cast<const float4*>(&X[(size_t)kk * xstride + x0 + m4 * 4]);
            }
        }
        const float* Xb = Xs + (kc & 1) * (16 * 128);
#pragma unroll
        for (int k = 0; k < 16; k++) {
            float4 a4 = *reinterpret_cast<const float4*>(&Xb[k * 128 + tm * 4]);
            ull ad0 = pk2(a4.x, a4.x), ad1 = pk2(a4.y, a4.y);
            ull ad2 = pk2(a4.z, a4.z), ad3 = pk2(a4.w, a4.w);
            const float* Wk = Ws + (kc * 16 + k) * 128 + n0;
#pragma unroll
            for (int c4 = 0; c4 < 4; c4++) {
                ulonglong2 bp = *reinterpret_cast<const ulonglong2*>(Wk + c4 * 4);
                fma2(acc[0][2 * c4 + 0], ad0, bp.x);
                fma2(acc[0][2 * c4 + 1], ad0, bp.y);
                fma2(acc[1][2 * c4 + 0], ad1, bp.x);
                fma2(acc[1][2 * c4 + 1], ad1, bp.y);
                fma2(acc[2][2 * c4 + 0], ad2, bp.x);
                fma2(acc[2][2 * c4 + 1], ad2, bp.y);
                fma2(acc[3][2 * c4 + 0], ad3, bp.x);
                fma2(acc[3][2 * c4 + 1], ad3, bp.y);
            }
        }
        if (kc < 7) {
            float* Xn = Xs + ((kc + 1) & 1) * (16 * 128);
            int f0 = tid * 2;
#pragma unroll
            for (int j = 0; j < 2; j++)
                reinterpret_cast<float4*>(Xn)[f0 + j - 0] = pre[j];
            __syncthreads();
        }
    }

#pragma unroll
    for (int i = 0; i < 4; i++)
#pragma unroll
        for (int c = 0; c < 8; c++) upk2(acc[i][c], va[i][2 * c], va[i][2 * c + 1]);
}

// ---------------- kernel 2: pointwise 1x1 GEMM ----------------
__global__ __launch_bounds__(256, 2) void pw_kernel(
    const float* __restrict__ bq_, const float* __restrict__ bk_,
    const float* __restrict__ bv_)
{
    int pix0 = blockIdx.x * 128;
    int t = blockIdx.y, proj = blockIdx.z;
    const float* bias = (proj == 0) ? bq_ : (proj == 1) ? bk_ : bv_;
    const float* X = &g_dw[proj][t][0][0];

    float va[4][16];
    gemm_core(&g_WT[proj][0][0], bias, X, HW, pix0, va);

    const int tm = threadIdx.x & 31, tn = threadIdx.x >> 5;
    const int n0 = tn * 16;

    if (proj == 0) {
#pragma unroll
        for (int i = 0; i < 4; i++)
#pragma unroll
            for (int c2 = 0; c2 < 16; c2++) va[i][c2] *= QSCALE;
    }

    if (proj < 2) {
        float* dst = ((proj == 0) ? g_q : g_k) + t * NC * HW;
#pragma unroll
        for (int c2 = 0; c2 < 16; c2++)
            *reinterpret_cast<float4*>(&dst[(n0 + c2) * HW + pix0 + tm * 4]) =
                make_float4(va[0][c2], va[1][c2], va[2][c2], va[3][c2]);
    } else {
        int h = n0 >> 5, dd = n0 & 31;
#pragma unroll
        for (int i = 0; i < 4; i++) {
            int pix = pix0 + tm * 4 + i;
            float* vp = &g_vT[((size_t)(t * HEADS + h) * HW + pix) * HD + dd];
#pragma unroll
            for (int j = 0; j < 4; j++)
                *reinterpret_cast<float4*>(&vp[j * 4]) =
                    make_float4(va[i][4 * j], va[i][4 * j + 1], va[i][4 * j + 2], va[i][4 * j + 3]);
        }
    }
}

// ---------------- kernel 4: final projection GEMM ----------------
__global__ __launch_bounds__(256, 2) void proj_kernel(
    const float* __restrict__ pb, float* __restrict__ out)
{
    int q0 = blockIdx.x * 128;
    int t = q0 / HW, hw0 = q0 - t * HW;

    float va[4][16];
    gemm_core(&g_WT[3][0][0], pb, g_att, NQ, q0, va);

    const int tm = threadIdx.x & 31, tn = threadIdx.x >> 5;
    const int n0 = tn * 16;
#pragma unroll
    for (int c2 = 0; c2 < 16; c2++)
        *reinterpret_cast<float4*>(&out[(size_t)(t * NC + n0 + c2) * HW + hw0 + tm * 4]) =
            make_float4(va[0][c2], va[1][c2], va[2][c2], va[3][c2]);
}

// ---------------- kernel 3: non-local attention ----------------
#define CE(i, j) do { unsigned _a = key[i], _b = key[j]; \
    key[i] = (_a > _b) ? _a : _b; key[j] = (_a > _b) ? _b : _a; } while (0)

#define SORT8(o) do { \
    CE(o+0,o+1); CE(o+2,o+3); CE(o+4,o+5); CE(o+6,o+7); \
    CE(o+0,o+2); CE(o+1,o+3); CE(o+4,o+6); CE(o+5,o+7); \
    CE(o+1,o+2); CE(o+5,o+6); \
    CE(o+0,o+4); CE(o+1,o+5); CE(o+2,o+6); CE(o+3,o+7); \
    CE(o+2,o+4); CE(o+3,o+5); \
    CE(o+1,o+2); CE(o+3,o+4); CE(o+5,o+6); } while (0)

#define BM8(o) do { \
    CE(o+0,o+4); CE(o+1,o+5); CE(o+2,o+6); CE(o+3,o+7); \
    CE(o+0,o+2); CE(o+1,o+3); CE(o+4,o+6); CE(o+5,o+7); \
    CE(o+0,o+1); CE(o+2,o+3); CE(o+4,o+5); CE(o+6,o+7); } while (0)

#define MERGE16(o) do { \
    CE(o+0,o+15); CE(o+1,o+14); CE(o+2,o+13); CE(o+3,o+12); \
    CE(o+4,o+11); CE(o+5,o+10); CE(o+6,o+9);  CE(o+7,o+8); \
    BM8(o); BM8(o+8); } while (0)

#define SORTB16(o) do { \
    CE(o+0,o+8);  CE(o+1,o+9);  CE(o+2,o+10); CE(o+3,o+11); \
    CE(o+4,o+12); CE(o+5,o+13); CE(o+6,o+14); CE(o+7,o+15); \
    BM8(o); BM8(o+8); } while (0)

__global__ __launch_bounds__(256, 2) void attn_kernel()
{
    extern __shared__ float ks[];
    const int tid = threadIdx.x;
    const int tx = tid & 31, ty = tid >> 5;
    const int tcx = (blockIdx.x % 3) * TW, trow = (blockIdx.x / 3) * TH;
    const int h = blockIdx.y, t = blockIdx.z;
    const int base = (t * NC + h * HD) * HW;
    const int br = trow - 4, bc = tcx - 4;

    // stage reflected k halo, d-quads interleaved
    for (int idx = tid; idx < 8 * HP; idx += 256) {
        int d4 = idx / HP, lp = idx - d4 * HP;
        int lr = lp / HC, lc = lp - lr * HC;
        int ri = refl(br + lr), rj = refl(bc + lc);
        const float* gp = g_k + base + (d4 * 4) * HW + ri * NW + rj;
        reinterpret_cast<float4*>(ks)[idx] =
            make_float4(gp[0], gp[HW], gp[2 * HW], gp[3 * HW]);
    }
    __syncthreads();

    const int gi = trow + ty, gj = tcx + tx;
    const int pix = gi * NW + gj;

    ull q2[16];
#pragma unroll
    for (int d2 = 0; d2 < 16; d2++)
        q2[d2] = pk2(g_q[base + (2 * d2) * HW + pix], g_q[base + (2 * d2 + 1) * HW + pix]);

    unsigned key[64];
#pragma unroll
    for (int a = 0; a < 8; a++) {
#pragma unroll
        for (int b = 0; b < 8; b++) {
            int lp = (ty + a) * HC + (tx + b);
            const float4* kp = reinterpret_cast<const float4*>(ks) + lp;
            ull s0 = 0ull, s1 = 0ull;
#pragma unroll
            for (int d4 = 0; d4 < 8; d4++) {
                float4 kv = kp[d4 * HP];
                fma2(s0, q2[2 * d4],     pk2(kv.x, kv.y));
                fma2(s1, q2[2 * d4 + 1], pk2(kv.z, kv.w));
            }
            float x0, x1, y0, y1;
            upk2(s0, x0, x1); upk2(s1, y0, y1);
            float s = (x0 + y0) + (x1 + y1);
            unsigned u = __float_as_uint(s);
            unsigned kk = (u & 0x80000000u) ? ~u : (u | 0x80000000u);
            key[a * 8 + b] = (kk & 0xFFFFFFC0u) | (unsigned)(a * 8 + b);
        }
    }

    SORT8(0); SORT8(8); SORT8(16); SORT8(24);
    SORT8(32); SORT8(40); SORT8(48); SORT8(56);
    MERGE16(0); MERGE16(16); MERGE16(32); MERGE16(48);
#pragma unroll
    for (int i = 0; i < 16; i++) { unsigned b2 = key[31 - i]; if (b2 > key[i]) key[i] = b2; }
    SORTB16(0);
#pragma unroll
    for (int i = 0; i < 16; i++) { unsigned b2 = key[63 - i]; if (b2 > key[32 + i]) key[32 + i] = b2; }
    SORTB16(32);
    unsigned mxkey = (key[0] > key[32]) ? key[0] : key[32];
#pragma unroll
    for (int i = 0; i < 16; i++) { unsigned b2 = key[47 - i]; if (b2 > key[i]) key[i] = b2; }

    unsigned mu = (mxkey & 0x80000000u) ? (mxkey ^ 0x80000000u) : ~mxkey;
    float mxv = __uint_as_float(mu);

    const float* vbase = g_vT + (size_t)(t * HEADS + h) * HW * HD;
    ull acc2[16];
#pragma unroll
    for (int c = 0; c < 16; c++) acc2[c] = 0ull;
    float wsum = 0.f;

#pragma unroll
    for (int p = 0; p < 16; p++) {
        unsigned kk = key[p];
        int ci = kk & 63;
        unsigned u = (kk & 0x80000000u) ? (kk ^ 0x80000000u) : ~kk;
        float f = __uint_as_float(u);
        float e = __expf(f - mxv);
        wsum += e;
        int ri = refl(br + ty + (ci >> 3));
        int rj = refl(bc + tx + (ci & 7));
        const ull* vp = reinterpret_cast<const ull*>(vbase + (ri * NW + rj) * HD);
        ull e2 = pk2(e, e);
#pragma unroll
        for (int c = 0; c < 16; c++) fma2(acc2[c], e2, __ldg(vp + c));
    }

    float inv = 1.f / wsum;
    const int qg = t * HW + pix;
#pragma unroll
    for (int c = 0; c < 16; c++) {
        float lo, hi;
        upk2(acc2[c], lo, hi);
        g_att[(size_t)(h * HD + 2 * c) * NQ + qg] = lo * inv;
        g_att[(size_t)(h * HD + 2 * c + 1) * NQ + qg] = hi * inv;
    }
}

// ---------------- launch ----------------
extern "C" void kernel_launch(void* const* d_in, const int* in_sizes, int n_in,
                              void* d_out, int out_size)
{
    const float* vid    = (const float*)d_in[0];
    const float* wq_dw  = (const float*)d_in[1];
    const float* wq_pw  = (const float*)d_in[2];
    const float* bq     = (const float*)d_in[3];
    const float* wk_dw  = (const float*)d_in[4];
    const float* wk_pw  = (const float*)d_in[5];
    const float* bk     = (const float*)d_in[6];
    const float* wv_dw  = (const float*)d_in[7];
    const float* wv_pw  = (const float*)d_in[8];
    const float* bv     = (const float*)d_in[9];
    const float* proj_w = (const float*)d_in[10];
    const float* proj_b = (const float*)d_in[11];
    float* out = (float*)d_out;

    const int attn_smem = HD * HP * (int)sizeof(float);      // 74880
    const int gemm_smem = (NC * NC + 2 * 16 * NC) * (int)sizeof(float);  // 81920
    cudaFuncSetAttribute(attn_kernel, cudaFuncAttributeMaxDynamicSharedMemorySize, attn_smem);
    cudaFuncSetAttribute(pw_kernel, cudaFuncAttributeMaxDynamicSharedMemorySize, gemm_smem);
    cudaFuncSetAttribute(proj_kernel, cudaFuncAttributeMaxDynamicSharedMemorySize, gemm_smem);

    wt_kernel<<<dim3(16, 4), 256>>>(wq_pw, wk_pw, wv_pw, proj_w);
    dw_kernel<<<dim3(9, 2, 16), 256>>>(vid, wq_dw, wk_dw, wv_dw);
    pw_kernel<<<dim3(72, 2, 3), 256, gemm_smem>>>(bq, bk, bv);
    attn_kernel<<<dim3(36, 4, 2), 256, attn_smem>>>();
    proj_kernel<<<dim3(144, 1, 1), 256, gemm_smem>>>(proj_b, out);
}

// round 5
// speedup vs baseline: 2.1283x; 1.3229x over previous
#include <cuda_runtime.h>
#include <cstdint>

#define NT 2
#define NC 128
#define NH 96
#define NW 96
#define HW 9216        // 96*96
#define NQ 18432       // NT*HW
#define HEADS 4
#define HD 32
#define QSCALE 0.17677669529663687f

// attention tile: 32 wide x 8 high
#define TW 32
#define TH 8
#define HC 39          // TW + 7
#define HR 15          // TH + 7
#define HP 585         // HR*HC

typedef unsigned long long ull;

// ---------------- scratch ----------------
__device__ __align__(16) float g_dw[3][NT][NC][HW];          // depthwise results q/k/v
__device__ __align__(16) float g_q[NT * NC * HW];            // [t*128+c][pix]
__device__ __align__(16) float g_k[NT * NC * HW];            // [t*128+c][pix]
__device__ __align__(16) float g_vT[NT * HEADS * HW * HD];   // [t][h][pix][d]
__device__ __align__(16) float g_att[NC * NQ];               // [c][q]  channel-major
__device__ __align__(16) float g_WT[4][NC][NC];              // transposed weights [k][n]

// ---------------- f32x2 helpers ----------------
__device__ __forceinline__ ull pk2(float lo, float hi) {
    ull r;
    asm("mov.b64 %0, {%1, %2};" : "=l"(r) : "f"(lo), "f"(hi));
    return r;
}
__device__ __forceinline__ void upk2(ull v, float& lo, float& hi) {
    asm("mov.b64 {%0, %1}, %2;" : "=f"(lo), "=f"(hi) : "l"(v));
}
__device__ __forceinline__ void fma2(ull& d, ull a, ull b) {
    asm("fma.rn.f32x2 %0, %1, %2, %0;" : "+l"(d) : "l"(a), "l"(b));
}
__device__ __forceinline__ int refl(int i) {
    i = (i < 0) ? -i : i;
    return (i > 95) ? 190 - i : i;
}

// ---------------- kernel 0: transpose weights into [k][n] ----------------
__global__ __launch_bounds__(256) void wt_kernel(
    const float* __restrict__ w0, const float* __restrict__ w1,
    const float* __restrict__ w2, const float* __restrict__ w3)
{
    __shared__ float tile[32][33];
    const float* srcs[4] = {w0, w1, w2, w3};
    int m = blockIdx.y;
    const float* W = srcs[m];
    int tr = blockIdx.x >> 2, tc = blockIdx.x & 3;   // 4x4 tiles of 32x32
    int tx = threadIdx.x & 31, ty = threadIdx.x >> 5;
#pragma unroll
    for (int i = 0; i < 4; i++)
        tile[ty * 4 + i][tx] = W[(tr * 32 + ty * 4 + i) * NC + tc * 32 + tx];
    __syncthreads();
#pragma unroll
    for (int i = 0; i < 4; i++)
        g_WT[m][tc * 32 + ty * 4 + i][tr * 32 + tx] = tile[tx][ty * 4 + i];
}

// ---------------- kernel 1: depthwise 3x3, zero-pad SAME ----------------
__global__ __launch_bounds__(256) void dw_kernel(
    const float* __restrict__ vid,
    const float* __restrict__ wq, const float* __restrict__ wk,
    const float* __restrict__ wv)
{
    int tid = threadIdx.x;
    int tx = tid & 31, ty = tid >> 5;
    int tilec = (blockIdx.x % 3) * 32, tiler = (blockIdx.x / 3) * 32;
    int t = blockIdx.y, cg = blockIdx.z;
    int gj = tilec + tx;
    int r0 = tiler + ty * 4;

    for (int cc = 0; cc < 8; cc++) {
        int c = cg * 8 + cc;
        const float* xp = vid + (t * NC + c) * HW;
        float x[6][3];
#pragma unroll
        for (int rr = 0; rr < 6; rr++) {
            int yy = r0 + rr - 1;
            bool yok = (yy >= 0 && yy < NH);
#pragma unroll
            for (int jj = 0; jj < 3; jj++) {
                int xxc = gj + jj - 1;
                x[rr][jj] = (yok && xxc >= 0 && xxc < NW) ? xp[yy * NW + xxc] : 0.f;
            }
        }
        const float* wqc = wq + c * 9;
        const float* wkc = wk + c * 9;
        const float* wvc = wv + c * 9;
        float wqr[9], wkr[9], wvr[9];
#pragma unroll
        for (int i = 0; i < 9; i++) { wqr[i] = wqc[i]; wkr[i] = wkc[i]; wvr[i] = wvc[i]; }
#pragma unroll
        for (int p = 0; p < 4; p++) {
            float sq = 0.f, sk = 0.f, sv = 0.f;
#pragma unroll
            for (int ky = 0; ky < 3; ky++)
#pragma unroll
                for (int kx = 0; kx < 3; kx++) {
                    float xv = x[p + ky][kx];
                    sq = fmaf(xv, wqr[ky * 3 + kx], sq);
                    sk = fmaf(xv, wkr[ky * 3 + kx], sk);
                    sv = fmaf(xv, wvr[ky * 3 + kx], sv);
                }
            int pix = (r0 + p) * NW + gj;
            g_dw[0][t][c][pix] = sq;
            g_dw[1][t][c][pix] = sk;
            g_dw[2][t][c][pix] = sv;
        }
    }
}

// ================= GEMM core =================
// dyn smem: Ws[128][128] (64KB) then Xs[2][16][128] (16KB)
__device__ __forceinline__ void gemm_core(
    const float* __restrict__ WT, const float* __restrict__ bias,
    const float* __restrict__ X, int xstride, int x0,
    float (&va)[4][16])
{
    extern __shared__ float sm[];
    float* Ws = sm;                 // [128][128]
    float* Xs = sm + NC * NC;       // [2][16][128]
    const int tid = threadIdx.x;
    const int tm = tid & 31, tn = tid >> 5;
    const int n0 = tn * 16;

#pragma unroll
    for (int i = 0; i < 16; i++)
        reinterpret_cast<float4*>(Ws)[tid + i * 256] =
            reinterpret_cast<const float4*>(WT)[tid + i * 256];

    {
        int f0 = tid * 2;
#pragma unroll
        for (int j = 0; j < 2; j++) {
            int f = f0 + j, kk = f >> 5, m4 = f & 31;
            reinterpret_cast<float4*>(Xs)[f] =
                *reinterpret_cast<const float4*>(&X[(size_t)kk * xstride + x0 + m4 * 4]);
        }
    }
    __syncthreads();

    ull acc[4][8];
#pragma unroll
    for (int c = 0; c < 8; c++) {
        ull b = pk2(bias[n0 + 2 * c], bias[n0 + 2 * c + 1]);
#pragma unroll
        for (int i = 0; i < 4; i++) acc[i][c] = b;
    }

#pragma unroll 1
    for (int kc = 0; kc < 8; kc++) {
        float4 pre[2];
        if (kc < 7) {
            int f0 = tid * 2;
#pragma unroll
            for (int j = 0; j < 2; j++) {
                int f = f0 + j, kk = (kc + 1) * 16 + (f >> 5), m4 = f & 31;
                pre[j] = *reinterpret_cast<const float4*>(&X[(size_t)kk * xstride + x0 + m4 * 4]);
            }
        }
        const float* Xb = Xs + (kc & 1) * (16 * 128);
#pragma unroll
        for (int k = 0; k < 16; k++) {
            float4 a4 = *reinterpret_cast<const float4*>(&Xb[k * 128 + tm * 4]);
            ull ad0 = pk2(a4.x, a4.x), ad1 = pk2(a4.y, a4.y);
            ull ad2 = pk2(a4.z, a4.z), ad3 = pk2(a4.w, a4.w);
            const float* Wk = Ws + (kc * 16 + k) * 128 + n0;
#pragma unroll
            for (int c4 = 0; c4 < 4; c4++) {
                ulonglong2 bp = *reinterpret_cast<const ulonglong2*>(Wk + c4 * 4);
                fma2(acc[0][2 * c4 + 0], ad0, bp.x);
                fma2(acc[0][2 * c4 + 1], ad0, bp.y);
                fma2(acc[1][2 * c4 + 0], ad1, bp.x);
                fma2(acc[1][2 * c4 + 1], ad1, bp.y);
                fma2(acc[2][2 * c4 + 0], ad2, bp.x);
                fma2(acc[2][2 * c4 + 1], ad2, bp.y);
                fma2(acc[3][2 * c4 + 0], ad3, bp.x);
                fma2(acc[3][2 * c4 + 1], ad3, bp.y);
            }
        }
        if (kc < 7) {
            float* Xn = Xs + ((kc + 1) & 1) * (16 * 128);
            int f0 = tid * 2;
#pragma unroll
            for (int j = 0; j < 2; j++)
                reinterpret_cast<float4*>(Xn)[f0 + j] = pre[j];
            __syncthreads();
        }
    }

#pragma unroll
    for (int i = 0; i < 4; i++)
#pragma unroll
        for (int c = 0; c < 8; c++) upk2(acc[i][c], va[i][2 * c], va[i][2 * c + 1]);
}

// ---------------- kernel 2: pointwise 1x1 GEMM ----------------
__global__ __launch_bounds__(256, 2) void pw_kernel(
    const float* __restrict__ bq_, const float* __restrict__ bk_,
    const float* __restrict__ bv_)
{
    int pix0 = blockIdx.x * 128;
    int t = blockIdx.y, proj = blockIdx.z;
    const float* bias = (proj == 0) ? bq_ : (proj == 1) ? bk_ : bv_;
    const float* X = &g_dw[proj][t][0][0];

    float va[4][16];
    gemm_core(&g_WT[proj][0][0], bias, X, HW, pix0, va);

    const int tm = threadIdx.x & 31, tn = threadIdx.x >> 5;
    const int n0 = tn * 16;

    if (proj == 0) {
#pragma unroll
        for (int i = 0; i < 4; i++)
#pragma unroll
            for (int c2 = 0; c2 < 16; c2++) va[i][c2] *= QSCALE;
    }

    if (proj < 2) {
        float* dst = ((proj == 0) ? g_q : g_k) + t * NC * HW;
#pragma unroll
        for (int c2 = 0; c2 < 16; c2++)
            *reinterpret_cast<float4*>(&dst[(n0 + c2) * HW + pix0 + tm * 4]) =
                make_float4(va[0][c2], va[1][c2], va[2][c2], va[3][c2]);
    } else {
        int h = n0 >> 5, dd = n0 & 31;
#pragma unroll
        for (int i = 0; i < 4; i++) {
            int pix = pix0 + tm * 4 + i;
            float* vp = &g_vT[((size_t)(t * HEADS + h) * HW + pix) * HD + dd];
#pragma unroll
            for (int j = 0; j < 4; j++)
                *reinterpret_cast<float4*>(&vp[j * 4]) =
                    make_float4(va[i][4 * j], va[i][4 * j + 1], va[i][4 * j + 2], va[i][4 * j + 3]);
        }
    }
}

// ---------------- kernel 4: final projection GEMM ----------------
__global__ __launch_bounds__(256, 2) void proj_kernel(
    const float* __restrict__ pb, float* __restrict__ out)
{
    int q0 = blockIdx.x * 128;
    int t = q0 / HW, hw0 = q0 - t * HW;

    float va[4][16];
    gemm_core(&g_WT[3][0][0], pb, g_att, NQ, q0, va);

    const int tm = threadIdx.x & 31, tn = threadIdx.x >> 5;
    const int n0 = tn * 16;
#pragma unroll
    for (int c2 = 0; c2 < 16; c2++)
        *reinterpret_cast<float4*>(&out[(size_t)(t * NC + n0 + c2) * HW + hw0 + tm * 4]) =
            make_float4(va[0][c2], va[1][c2], va[2][c2], va[3][c2]);
}

// ---------------- kernel 3: non-local attention ----------------
#define CE(i, j) do { unsigned _a = key[i], _b = key[j]; \
    key[i] = (_a > _b) ? _a : _b; key[j] = (_a > _b) ? _b : _a; } while (0)

#define SORT8(o) do { \
    CE(o+0,o+1); CE(o+2,o+3); CE(o+4,o+5); CE(o+6,o+7); \
    CE(o+0,o+2); CE(o+1,o+3); CE(o+4,o+6); CE(o+5,o+7); \
    CE(o+1,o+2); CE(o+5,o+6); \
    CE(o+0,o+4); CE(o+1,o+5); CE(o+2,o+6); CE(o+3,o+7); \
    CE(o+2,o+4); CE(o+3,o+5); \
    CE(o+1,o+2); CE(o+3,o+4); CE(o+5,o+6); } while (0)

#define BM8(o) do { \
    CE(o+0,o+4); CE(o+1,o+5); CE(o+2,o+6); CE(o+3,o+7); \
    CE(o+0,o+2); CE(o+1,o+3); CE(o+4,o+6); CE(o+5,o+7); \
    CE(o+0,o+1); CE(o+2,o+3); CE(o+4,o+5); CE(o+6,o+7); } while (0)

#define MERGE16(o) do { \
    CE(o+0,o+15); CE(o+1,o+14); CE(o+2,o+13); CE(o+3,o+12); \
    CE(o+4,o+11); CE(o+5,o+10); CE(o+6,o+9);  CE(o+7,o+8); \
    BM8(o); BM8(o+8); } while (0)

#define SORTB16(o) do { \
    CE(o+0,o+8);  CE(o+1,o+9);  CE(o+2,o+10); CE(o+3,o+11); \
    CE(o+4,o+12); CE(o+5,o+13); CE(o+6,o+14); CE(o+7,o+15); \
    BM8(o); BM8(o+8); } while (0)

__global__ __launch_bounds__(256, 2) void attn_kernel()
{
    extern __shared__ float sm[];
    const int tid = threadIdx.x;
    const int tx = tid & 31, ty = tid >> 5;
    const int tcx = (blockIdx.x % 3) * TW, trow = (blockIdx.x / 3) * TH;
    const int h = blockIdx.y, t = blockIdx.z;
    const int base = (t * NC + h * HD) * HW;
    const int br = trow - 4, bc = tcx - 4;

    // phase A: stage reflected k halo, d-quads interleaved: float4 [d4][lp]
    for (int idx = tid; idx < 8 * HP; idx += 256) {
        int d4 = idx / HP, lp = idx - d4 * HP;
        int lr = lp / HC, lc = lp - lr * HC;
        int ri = refl(br + lr), rj = refl(bc + lc);
        const float* gp = g_k + base + (d4 * 4) * HW + ri * NW + rj;
        reinterpret_cast<float4*>(sm)[idx] =
            make_float4(gp[0], gp[HW], gp[2 * HW], gp[3 * HW]);
    }
    __syncthreads();

    const int gi = trow + ty, gj = tcx + tx;
    const int pix = gi * NW + gj;

    ull q2[16];
#pragma unroll
    for (int d2 = 0; d2 < 16; d2++)
        q2[d2] = pk2(g_q[base + (2 * d2) * HW + pix], g_q[base + (2 * d2 + 1) * HW + pix]);

    unsigned key[64];
#pragma unroll
    for (int a = 0; a < 8; a++) {
#pragma unroll
        for (int b = 0; b < 8; b++) {
            int lp = (ty + a) * HC + (tx + b);
            const float4* kp = reinterpret_cast<const float4*>(sm) + lp;
            ull s0 = 0ull, s1 = 0ull;
#pragma unroll
            for (int d4 = 0; d4 < 8; d4++) {
                float4 kv = kp[d4 * HP];
                fma2(s0, q2[2 * d4],     pk2(kv.x, kv.y));
                fma2(s1, q2[2 * d4 + 1], pk2(kv.z, kv.w));
            }
            float x0, x1, y0, y1;
            upk2(s0, x0, x1); upk2(s1, y0, y1);
            float s = (x0 + y0) + (x1 + y1);
            unsigned u = __float_as_uint(s);
            unsigned kk = (u & 0x80000000u) ? ~u : (u | 0x80000000u);
            key[a * 8 + b] = (kk & 0xFFFFFFC0u) | (unsigned)(a * 8 + b);
        }
    }
    __syncthreads();   // all k reads complete before overwrite

    // phase B: stage reflected v halo, pixel-major, XOR slot swizzle: float4 [lp][d4^(lp&7)]
    const float* vbase = g_vT + (size_t)(t * HEADS + h) * HW * HD;
    for (int idx = tid; idx < 8 * HP; idx += 256) {
        int lp = idx >> 3, d4 = idx & 7;
        int lr = lp / HC, lc = lp - lr * HC;
        int ri = refl(br + lr), rj = refl(bc + lc);
        float4 vv = *reinterpret_cast<const float4*>(&vbase[(size_t)(ri * NW + rj) * HD + d4 * 4]);
        reinterpret_cast<float4*>(sm)[lp * 8 + (d4 ^ (lp & 7))] = vv;
    }
    __syncthreads();

    // top-16 selection (sorting networks on packed keys)
    SORT8(0); SORT8(8); SORT8(16); SORT8(24);
    SORT8(32); SORT8(40); SORT8(48); SORT8(56);
    MERGE16(0); MERGE16(16); MERGE16(32); MERGE16(48);
#pragma unroll
    for (int i = 0; i < 16; i++) { unsigned b2 = key[31 - i]; if (b2 > key[i]) key[i] = b2; }
    SORTB16(0);
#pragma unroll
    for (int i = 0; i < 16; i++) { unsigned b2 = key[63 - i]; if (b2 > key[32 + i]) key[32 + i] = b2; }
    SORTB16(32);
    unsigned mxkey = (key[0] > key[32]) ? key[0] : key[32];
#pragma unroll
    for (int i = 0; i < 16; i++) { unsigned b2 = key[47 - i]; if (b2 > key[i]) key[i] = b2; }

    unsigned mu = (mxkey & 0x80000000u) ? (mxkey ^ 0x80000000u) : ~mxkey;
    float mxv = __uint_as_float(mu);

    // weights + halo-local pixel index per pick (halo already reflected -> no refl here)
    float wgt[16]; int lps[16];
    float wsum = 0.f;
#pragma unroll
    for (int p = 0; p < 16; p++) {
        unsigned kk = key[p];
        int ci = kk & 63;
        unsigned u = (kk & 0x80000000u) ? (kk ^ 0x80000000u) : ~kk;
        float e = __expf(__uint_as_float(u) - mxv);
        wsum += e;
        wgt[p] = e;
        lps[p] = (ty + (ci >> 3)) * HC + (tx + (ci & 7));
    }

    // gather v from smem
    ull acc2[16];
#pragma unroll
    for (int c = 0; c < 16; c++) acc2[c] = 0ull;
#pragma unroll
    for (int p = 0; p < 16; p++) {
        int lp = lps[p];
        const float4* vp = reinterpret_cast<const float4*>(sm) + lp * 8;
        int sw = lp & 7;
        ull e2 = pk2(wgt[p], wgt[p]);
#pragma unroll
        for (int d4 = 0; d4 < 8; d4++) {
            float4 vv = vp[d4 ^ sw];
            fma2(acc2[2 * d4],     e2, pk2(vv.x, vv.y));
            fma2(acc2[2 * d4 + 1], e2, pk2(vv.z, vv.w));
        }
    }

    float inv = 1.f / wsum;
    const int qg = t * HW + pix;
#pragma unroll
    for (int c = 0; c < 16; c++) {
        float lo, hi;
        upk2(acc2[c], lo, hi);
        g_att[(size_t)(h * HD + 2 * c) * NQ + qg] = lo * inv;
        g_att[(size_t)(h * HD + 2 * c + 1) * NQ + qg] = hi * inv;
    }
}

// ---------------- launch ----------------
extern "C" void kernel_launch(void* const* d_in, const int* in_sizes, int n_in,
                              void* d_out, int out_size)
{
    const float* vid    = (const float*)d_in[0];
    const float* wq_dw  = (const float*)d_in[1];
    const float* wq_pw  = (const float*)d_in[2];
    const float* bq     = (const float*)d_in[3];
    const float* wk_dw  = (const float*)d_in[4];
    const float* wk_pw  = (const float*)d_in[5];
    const float* bk     = (const float*)d_in[6];
    const float* wv_dw  = (const float*)d_in[7];
    const float* wv_pw  = (const float*)d_in[8];
    const float* bv     = (const float*)d_in[9];
    const float* proj_w = (const float*)d_in[10];
    const float* proj_b = (const float*)d_in[11];
    float* out = (float*)d_out;

    const int attn_smem = 8 * HP * 16;                        // 74880
    const int gemm_smem = (NC * NC + 2 * 16 * NC) * (int)sizeof(float);  // 81920
    cudaFuncSetAttribute(attn_kernel, cudaFuncAttributeMaxDynamicSharedMemorySize, attn_smem);
    cudaFuncSetAttribute(pw_kernel, cudaFuncAttributeMaxDynamicSharedMemorySize, gemm_smem);
    cudaFuncSetAttribute(proj_kernel, cudaFuncAttributeMaxDynamicSharedMemorySize, gemm_smem);

    wt_kernel<<<dim3(16, 4), 256>>>(wq_pw, wk_pw, wv_pw, proj_w);
    dw_kernel<<<dim3(9, 2, 16), 256>>>(vid, wq_dw, wk_dw, wv_dw);
    pw_kernel<<<dim3(72, 2, 3), 256, gemm_smem>>>(bq, bk, bv);
    attn_kernel<<<dim3(36, 4, 2), 256, attn_smem>>>();
    proj_kernel<<<dim3(144, 1, 1), 256, gemm_smem>>>(proj_b, out);
}